// round 1
// baseline (speedup 1.0000x reference)
#include <cuda_runtime.h>
#include <math.h>

// ---------------------------------------------------------------------------
// DeepHeadClassifier fused pipeline, round 1 baseline.
//  B=65536, E=256, H=4, D=64, NC=7
//  K1  gemm<0>: qkv = stacked @ in_proj_w^T + b           [3B,768]
//  K2a attn   : per-row 3x3 attention over 4 heads -> ctx [3B,256]
//  K2b gemm<1>: att = ctx @ out_w^T + out_b + stacked     [3B,256]
//  K2c fuse   : LN1 per token, gate softmax, fused, LN2   [B,256]
//  K3a gemm<2>: h2 = GELU(h @ w1^T + b1)                  [B,256]
//  K3b gemm<3>: h3 = GELU(h2 @ w2^T + b2)                 [B,128]
//  K3c logit  : logits = h3 @ w3^T + b3                   [B,7]
// Output: [logits (B*7) | fused (B*256)]
// ---------------------------------------------------------------------------

typedef unsigned long long u64;

#define BMAX 65536

__device__ float g_qkv[(size_t)BMAX * 3 * 768];
__device__ float g_ctx[(size_t)BMAX * 3 * 256];
__device__ float g_x  [(size_t)BMAX * 3 * 256];
__device__ float g_h  [(size_t)BMAX * 256];
__device__ float g_h2 [(size_t)BMAX * 256];
__device__ float g_h3 [(size_t)BMAX * 128];

__device__ __forceinline__ u64 pack_dup(float a) {
    u64 r; unsigned ai = __float_as_uint(a);
    asm("mov.b64 %0, {%1, %2};" : "=l"(r) : "r"(ai), "r"(ai));
    return r;
}
__device__ __forceinline__ void ffma2(u64 &c, u64 a, u64 b) {
    asm("fma.rn.f32x2 %0, %1, %2, %3;" : "=l"(c) : "l"(a), "l"(b), "l"(c));
}
__device__ __forceinline__ u64 add2(u64 a, u64 b) {
    u64 r; asm("add.rn.f32x2 %0, %1, %2;" : "=l"(r) : "l"(a), "l"(b));
    return r;
}
__device__ __forceinline__ float geluf(float x) {
    return 0.5f * x * (1.0f + erff(x * 0.7071067811865476f));
}
__device__ __forceinline__ float wsum(float v) {
    #pragma unroll
    for (int o = 16; o > 0; o >>= 1) v += __shfl_xor_sync(0xffffffffu, v, o);
    return v;
}

// ---------------------------------------------------------------------------
// Tiled SGEMM with f32x2 FFMA2.  C[m,n] = sum_k A[m,k] * W[n,k] (+epilogue)
// BM=BN=128, BK=16, 256 threads, 8x8 per thread.
// MODE 0: A = gather(f_swin/f_maxvit/f_focal), C = g_qkv (ldc 768), +bias
// MODE 1: A = g_ctx,  C = g_x   (ldc 256), +bias +residual(stacked)
// MODE 2: A = g_h,    C = g_h2  (ldc 256), +bias, GELU
// MODE 3: A = g_h2,   C = g_h3  (ldc 128), +bias, GELU
// ---------------------------------------------------------------------------
template<int MODE>
__global__ __launch_bounds__(256)
void gemm_k(const float* __restrict__ W, const float* __restrict__ bias,
            const float* __restrict__ s0, const float* __restrict__ s1,
            const float* __restrict__ s2)
{
    const int BM = 128, BK = 16, K = 256;
    __shared__ __align__(16) float As[BK][BM];
    __shared__ __align__(16) float Bs[BK][BM];

    const int tid = threadIdx.x;
    const int m0 = blockIdx.y * BM;
    const int n0 = blockIdx.x * BM;

    const float* A = nullptr;
    float* C; int ldc;
    if constexpr (MODE == 0)      {              C = g_qkv; ldc = 768; }
    else if constexpr (MODE == 1) { A = g_ctx;   C = g_x;   ldc = 256; }
    else if constexpr (MODE == 2) { A = g_h;     C = g_h2;  ldc = 256; }
    else                          { A = g_h2;    C = g_h3;  ldc = 128; }

    const int tx = tid & 15, ty = tid >> 4;
    const int lrow = tid >> 2;        // 0..63
    const int lcol = (tid & 3) * 4;   // 0,4,8,12

    u64 acc[8][4];
    #pragma unroll
    for (int i = 0; i < 8; i++)
        #pragma unroll
        for (int j = 0; j < 4; j++) acc[i][j] = 0ULL;

    for (int k0 = 0; k0 < K; k0 += BK) {
        #pragma unroll
        for (int p = 0; p < 2; p++) {
            int r = lrow + p * 64;
            int m = m0 + r;
            const float* ap;
            if constexpr (MODE == 0) {
                int b = m / 3, t = m - b * 3;
                const float* s = (t == 0) ? s0 : (t == 1) ? s1 : s2;
                ap = s + (size_t)b * 256 + k0 + lcol;
            } else {
                ap = A + (size_t)m * 256 + k0 + lcol;
            }
            float4 v = *(const float4*)ap;
            As[lcol+0][r] = v.x; As[lcol+1][r] = v.y;
            As[lcol+2][r] = v.z; As[lcol+3][r] = v.w;
        }
        #pragma unroll
        for (int p = 0; p < 2; p++) {
            int r = lrow + p * 64;
            float4 v = *(const float4*)(W + (size_t)(n0 + r) * K + k0 + lcol);
            Bs[lcol+0][r] = v.x; Bs[lcol+1][r] = v.y;
            Bs[lcol+2][r] = v.z; Bs[lcol+3][r] = v.w;
        }
        __syncthreads();
        #pragma unroll
        for (int kk = 0; kk < BK; kk++) {
            float a[8];
            *(float4*)&a[0] = *(const float4*)&As[kk][ty * 8];
            *(float4*)&a[4] = *(const float4*)&As[kk][ty * 8 + 4];
            u64 b[4];
            const u64* bp = (const u64*)&Bs[kk][tx * 8];
            b[0] = bp[0]; b[1] = bp[1]; b[2] = bp[2]; b[3] = bp[3];
            #pragma unroll
            for (int i = 0; i < 8; i++) {
                u64 ad = pack_dup(a[i]);
                ffma2(acc[i][0], ad, b[0]);
                ffma2(acc[i][1], ad, b[1]);
                ffma2(acc[i][2], ad, b[2]);
                ffma2(acc[i][3], ad, b[3]);
            }
        }
        __syncthreads();
    }

    #pragma unroll
    for (int i = 0; i < 8; i++) {
        int m = m0 + ty * 8 + i;
        const float* srow = nullptr;
        if constexpr (MODE == 1) {
            int b = m / 3, t = m - b * 3;
            const float* s = (t == 0) ? s0 : (t == 1) ? s1 : s2;
            srow = s + (size_t)b * 256;
        }
        #pragma unroll
        for (int j = 0; j < 4; j++) {
            int n = n0 + tx * 8 + 2 * j;
            u64 v = add2(acc[i][j], *(const u64*)&bias[n]);
            if constexpr (MODE == 1) v = add2(v, *(const u64*)&srow[n]);
            if constexpr (MODE >= 2) {
                float lo = __uint_as_float((unsigned)v);
                float hi = __uint_as_float((unsigned)(v >> 32));
                lo = geluf(lo); hi = geluf(hi);
                v = ((u64)__float_as_uint(hi) << 32) | (u64)__float_as_uint(lo);
            }
            *(u64*)&C[(size_t)m * ldc + n] = v;
        }
    }
}

// ---------------------------------------------------------------------------
// K2a: attention. warp per row. lane handles dims [lane*8, lane*8+8);
// head h = lane/8, reduce within 8-lane groups (64 dims per head).
// ---------------------------------------------------------------------------
__global__ __launch_bounds__(256)
void attn_k(int B)
{
    int warp = threadIdx.x >> 5, lane = threadIdx.x & 31;
    int b = blockIdx.x * 8 + warp;
    if (b >= B) return;
    size_t base = (size_t)b * 3 * 768;
    int d0 = lane * 8;

    float q[3][8], k[3][8], v[3][8];
    #pragma unroll
    for (int t = 0; t < 3; t++) {
        const float* row = g_qkv + base + (size_t)t * 768;
        *(float4*)&q[t][0] = *(const float4*)(row + d0);
        *(float4*)&q[t][4] = *(const float4*)(row + d0 + 4);
        *(float4*)&k[t][0] = *(const float4*)(row + 256 + d0);
        *(float4*)&k[t][4] = *(const float4*)(row + 256 + d0 + 4);
        *(float4*)&v[t][0] = *(const float4*)(row + 512 + d0);
        *(float4*)&v[t][4] = *(const float4*)(row + 512 + d0 + 4);
    }
    float s[3][3];
    #pragma unroll
    for (int t = 0; t < 3; t++)
        #pragma unroll
        for (int u = 0; u < 3; u++) {
            float p = 0.f;
            #pragma unroll
            for (int j = 0; j < 8; j++) p += q[t][j] * k[u][j];
            p += __shfl_xor_sync(0xffffffffu, p, 1);
            p += __shfl_xor_sync(0xffffffffu, p, 2);
            p += __shfl_xor_sync(0xffffffffu, p, 4);
            s[t][u] = p * 0.125f;   // 1/sqrt(64)
        }
    #pragma unroll
    for (int t = 0; t < 3; t++) {
        float mx = fmaxf(s[t][0], fmaxf(s[t][1], s[t][2]));
        float e0 = expf(s[t][0] - mx);
        float e1 = expf(s[t][1] - mx);
        float e2 = expf(s[t][2] - mx);
        float inv = 1.f / (e0 + e1 + e2);
        float c[8];
        #pragma unroll
        for (int j = 0; j < 8; j++)
            c[j] = (e0 * v[0][j] + e1 * v[1][j] + e2 * v[2][j]) * inv;
        float* crow = g_ctx + ((size_t)b * 3 + t) * 256 + d0;
        *(float4*)crow       = *(float4*)&c[0];
        *(float4*)(crow + 4) = *(float4*)&c[4];
    }
}

// ---------------------------------------------------------------------------
// K2c: LN1 per token, gate softmax, fused output, LN2 -> g_h. warp per row.
// ---------------------------------------------------------------------------
__global__ __launch_bounds__(256)
void fuse_k(const float* __restrict__ s0, const float* __restrict__ s1,
            const float* __restrict__ s2,
            const float* __restrict__ ln1g, const float* __restrict__ ln1b,
            const float* __restrict__ gw,   const float* __restrict__ gb,
            const float* __restrict__ ln2g, const float* __restrict__ ln2b,
            float* __restrict__ out_fused, int B)
{
    int warp = threadIdx.x >> 5, lane = threadIdx.x & 31;
    int b = blockIdx.x * 8 + warp;
    if (b >= B) return;
    int d0 = lane * 8;
    const float* srcs[3] = {s0, s1, s2};

    float y[3][8];
    float gpart[3] = {0.f, 0.f, 0.f};
    #pragma unroll
    for (int t = 0; t < 3; t++) {
        float x[8];
        const float* row = g_x + ((size_t)b * 3 + t) * 256;
        *(float4*)&x[0] = *(const float4*)(row + d0);
        *(float4*)&x[4] = *(const float4*)(row + d0 + 4);
        float s = 0.f;
        #pragma unroll
        for (int j = 0; j < 8; j++) s += x[j];
        s = wsum(s);
        float mu = s * (1.f / 256.f);
        float vv = 0.f;
        #pragma unroll
        for (int j = 0; j < 8; j++) { float d = x[j] - mu; vv += d * d; }
        vv = wsum(vv);
        float rs = rsqrtf(vv * (1.f / 256.f) + 1e-5f);
        #pragma unroll
        for (int j = 0; j < 8; j++)
            y[t][j] = (x[j] - mu) * rs * ln1g[d0 + j] + ln1b[d0 + j];

        float iv[8];
        const float* in = srcs[t] + (size_t)b * 256;
        *(float4*)&iv[0] = *(const float4*)(in + d0);
        *(float4*)&iv[4] = *(const float4*)(in + d0 + 4);
        #pragma unroll
        for (int g = 0; g < 3; g++) {
            const float* wrow = gw + (size_t)g * 768 + t * 256 + d0;
            #pragma unroll
            for (int j = 0; j < 8; j++) gpart[g] += iv[j] * wrow[j];
        }
    }
    float gl[3];
    #pragma unroll
    for (int g = 0; g < 3; g++) gl[g] = wsum(gpart[g]) + gb[g];
    float mx = fmaxf(gl[0], fmaxf(gl[1], gl[2]));
    float e0 = expf(gl[0] - mx), e1 = expf(gl[1] - mx), e2 = expf(gl[2] - mx);
    float inv = 1.f / (e0 + e1 + e2);
    float w0 = e0 * inv, w1 = e1 * inv, w2 = e2 * inv;

    float f[8];
    #pragma unroll
    for (int j = 0; j < 8; j++)
        f[j] = w0 * y[0][j] + w1 * y[1][j] + w2 * y[2][j];
    if (out_fused) {
        float* orow = out_fused + (size_t)b * 256 + d0;
        *(float4*)orow       = *(float4*)&f[0];
        *(float4*)(orow + 4) = *(float4*)&f[4];
    }
    // LN2 -> g_h
    float s2v = 0.f;
    #pragma unroll
    for (int j = 0; j < 8; j++) s2v += f[j];
    s2v = wsum(s2v);
    float mu2 = s2v * (1.f / 256.f);
    float vv2 = 0.f;
    #pragma unroll
    for (int j = 0; j < 8; j++) { float d = f[j] - mu2; vv2 += d * d; }
    vv2 = wsum(vv2);
    float rs2 = rsqrtf(vv2 * (1.f / 256.f) + 1e-5f);
    float h[8];
    #pragma unroll
    for (int j = 0; j < 8; j++)
        h[j] = (f[j] - mu2) * rs2 * ln2g[d0 + j] + ln2b[d0 + j];
    float* hrow = g_h + (size_t)b * 256 + d0;
    *(float4*)hrow       = *(float4*)&h[0];
    *(float4*)(hrow + 4) = *(float4*)&h[4];
}

// ---------------------------------------------------------------------------
// K3c: logits = h3 @ w3^T + b3.  warp per row; lane holds 4 of 128 dims.
// ---------------------------------------------------------------------------
__global__ __launch_bounds__(256)
void logit_k(const float* __restrict__ w3, const float* __restrict__ b3,
             float* __restrict__ out, int B)
{
    int warp = threadIdx.x >> 5, lane = threadIdx.x & 31;
    int b = blockIdx.x * 8 + warp;
    if (b >= B) return;
    int d0 = lane * 4;
    float4 h = *(const float4*)(g_h3 + (size_t)b * 128 + d0);
    float r[7];
    #pragma unroll
    for (int j = 0; j < 7; j++) {
        float4 w = *(const float4*)(w3 + j * 128 + d0);
        float p = h.x * w.x + h.y * w.y + h.z * w.z + h.w * w.w;
        r[j] = wsum(p);
    }
    if (lane == 0) {
        #pragma unroll
        for (int j = 0; j < 7; j++) out[(size_t)b * 7 + j] = r[j] + b3[j];
    }
}

// ---------------------------------------------------------------------------
extern "C" void kernel_launch(void* const* d_in, const int* in_sizes, int n_in,
                              void* d_out, int out_size)
{
    const float* f_swin   = (const float*)d_in[0];
    const float* f_maxvit = (const float*)d_in[1];
    const float* f_focal  = (const float*)d_in[2];
    const float* in_proj_w = (const float*)d_in[3];
    const float* in_proj_b = (const float*)d_in[4];
    const float* out_w = (const float*)d_in[5];
    const float* out_b = (const float*)d_in[6];
    const float* ln1_g = (const float*)d_in[7];
    const float* ln1_b = (const float*)d_in[8];
    const float* gate_w = (const float*)d_in[9];
    const float* gate_b = (const float*)d_in[10];
    const float* ln2_g = (const float*)d_in[11];
    const float* ln2_b = (const float*)d_in[12];
    const float* w1 = (const float*)d_in[13];
    const float* b1 = (const float*)d_in[14];
    const float* w2 = (const float*)d_in[15];
    const float* b2 = (const float*)d_in[16];
    const float* w3 = (const float*)d_in[17];
    const float* b3 = (const float*)d_in[18];

    int B = in_sizes[0] / 256;
    if (B > BMAX) B = BMAX;

    float* outp = (float*)d_out;
    float* out_logits = outp;
    float* out_fused = (out_size >= B * 263) ? (outp + (size_t)B * 7) : nullptr;

    int rowsM  = 3 * B;              // 196608
    dim3 blk(256);

    // K1: qkv GEMM  [3B, 768]
    gemm_k<0><<<dim3(768 / 128, rowsM / 128), blk>>>(in_proj_w, in_proj_b,
                                                     f_swin, f_maxvit, f_focal);
    // K2a: attention
    attn_k<<<(B + 7) / 8, blk>>>(B);
    // K2b: out-proj + residual
    gemm_k<1><<<dim3(256 / 128, rowsM / 128), blk>>>(out_w, out_b,
                                                     f_swin, f_maxvit, f_focal);
    // K2c: LN1 + gate + fused + LN2
    fuse_k<<<(B + 7) / 8, blk>>>(f_swin, f_maxvit, f_focal,
                                 ln1_g, ln1_b, gate_w, gate_b, ln2_g, ln2_b,
                                 out_fused, B);
    // K3a: h2 = GELU(h @ w1^T + b1)
    gemm_k<2><<<dim3(256 / 128, B / 128), blk>>>(w1, b1, nullptr, nullptr, nullptr);
    // K3b: h3 = GELU(h2 @ w2^T + b2)
    gemm_k<3><<<dim3(128 / 128, B / 128), blk>>>(w2, b2, nullptr, nullptr, nullptr);
    // K3c: logits
    logit_k<<<(B + 7) / 8, blk>>>(w3, b3, out_logits, B);
}

// round 4
// speedup vs baseline: 2.4885x; 2.4885x over previous
#include <cuda_runtime.h>
#include <cuda_bf16.h>
#include <math.h>
#include <stdint.h>

typedef unsigned int u32;
typedef unsigned long long u64;

#define BMAX 65536

// ---------------------------------------------------------------------------
// Device scratch. "split" tensors are bf16 [rows, 512]: cols [0,256)=hi, lo after.
// ---------------------------------------------------------------------------
__device__ __nv_bfloat16 g_a  [(size_t)BMAX * 3 * 512];  // split features
__device__ float         g_qkv[(size_t)BMAX * 3 * 768];  // qkv fp32
__device__ __nv_bfloat16 g_ctx[(size_t)BMAX * 3 * 512];  // attention ctx, split
__device__ float         g_x  [(size_t)BMAX * 3 * 256];  // att_out + residual
__device__ __nv_bfloat16 g_hh [(size_t)BMAX * 512];      // LN2(fused), split
__device__ __nv_bfloat16 g_h2 [(size_t)BMAX * 512];      // GELU(h@w1), split
__device__ float         g_h3 [(size_t)BMAX * 128];      // GELU(h2@w2)
__device__ __nv_bfloat16 g_w  [(size_t)(768 + 256 + 256 + 128) * 512]; // split weights

#define WOFF_QKV 0
#define WOFF_OUT (768 * 512)
#define WOFF_W1  ((768 + 256) * 512)
#define WOFF_W2  ((768 + 512) * 512)

__device__ __forceinline__ u32 smem_u32(const void* p) {
    u32 a;
    asm("{ .reg .u64 t; cvta.to.shared.u64 t, %1; cvt.u32.u64 %0, t; }" : "=r"(a) : "l"(p));
    return a;
}
__device__ __forceinline__ float geluf(float x) {
    return 0.5f * x * (1.0f + erff(x * 0.7071067811865476f));
}
__device__ __forceinline__ float wsum(float v) {
    #pragma unroll
    for (int o = 16; o > 0; o >>= 1) v += __shfl_xor_sync(0xffffffffu, v, o);
    return v;
}
// split fp32 pair into (hi, lo) bf16x2 words
__device__ __forceinline__ void split2(float a, float b, u32& h, u32& l) {
    __nv_bfloat162 hh = __floats2bfloat162_rn(a, b);
    float ra = a - __bfloat162float(hh.x);
    float rb = b - __bfloat162float(hh.y);
    __nv_bfloat162 ll = __floats2bfloat162_rn(ra, rb);
    h = *reinterpret_cast<u32*>(&hh);
    l = *reinterpret_cast<u32*>(&ll);
}

// ---------------------------------------------------------------------------
// Conversion: fp32 [rows,256] -> bf16 split [rows,512]
// ---------------------------------------------------------------------------
__global__ __launch_bounds__(256)
void conv_feat_k(const float* __restrict__ s0, const float* __restrict__ s1,
                 const float* __restrict__ s2, int rows3)
{
    int id = blockIdx.x * 256 + threadIdx.x;
    if (id >= rows3 * 64) return;
    int row = id >> 6;
    int k = (id & 63) << 2;
    int b = row / 3, t = row - b * 3;
    const float* s = (t == 0) ? s0 : (t == 1) ? s1 : s2;
    float4 v = *(const float4*)(s + (size_t)b * 256 + k);
    u32 h0, l0, h1, l1;
    split2(v.x, v.y, h0, l0);
    split2(v.z, v.w, h1, l1);
    u32* hp = (u32*)&g_a[(size_t)row * 512 + k];
    u32* lp = (u32*)&g_a[(size_t)row * 512 + 256 + k];
    hp[0] = h0; hp[1] = h1;
    lp[0] = l0; lp[1] = l1;
}

__global__ __launch_bounds__(256)
void conv_w_k(const float* __restrict__ src, int rows, int woff)
{
    int id = blockIdx.x * 256 + threadIdx.x;
    if (id >= rows * 64) return;
    int row = id >> 6;
    int k = (id & 63) << 2;
    float4 v = *(const float4*)(src + (size_t)row * 256 + k);
    u32 h0, l0, h1, l1;
    split2(v.x, v.y, h0, l0);
    split2(v.z, v.w, h1, l1);
    __nv_bfloat16* dst = g_w + (size_t)woff + (size_t)row * 512;
    u32* hp = (u32*)(dst + k);
    u32* lp = (u32*)(dst + 256 + k);
    hp[0] = h0; hp[1] = h1;
    lp[0] = l0; lp[1] = l1;
}

// ---------------------------------------------------------------------------
// mma.sync bf16 GEMM with hi/lo split-K (virtual K=768, 12 BK=64 chunk pairs):
//   C = Ahi·Whi + Ahi·Wlo + Alo·Whi   (error ~ Alo·Wlo ~ 2^-16)
// 128x128 tile, SW128 swizzled smem, cp.async 2-stage, 8 warps.
// MODE 0: C=g_qkv (ldc 768), +bias
// MODE 1: C=g_x   (ldc 256), +bias +residual
// MODE 2: C=g_h2  (bf16 split), +bias, GELU
// MODE 3: C=g_h3  (ldc 128), +bias, GELU
// ---------------------------------------------------------------------------
__device__ __forceinline__ void ldsm4(u32 addr, u32& r0, u32& r1, u32& r2, u32& r3) {
    asm volatile("ldmatrix.sync.aligned.m8n8.x4.shared.b16 {%0,%1,%2,%3}, [%4];"
                 : "=r"(r0), "=r"(r1), "=r"(r2), "=r"(r3) : "r"(addr));
}
__device__ __forceinline__ void mma16816(float* c, const u32* a, u32 b0, u32 b1) {
    asm volatile(
        "mma.sync.aligned.m16n8k16.row.col.f32.bf16.bf16.f32 "
        "{%0,%1,%2,%3}, {%4,%5,%6,%7}, {%8,%9}, {%0,%1,%2,%3};"
        : "+f"(c[0]), "+f"(c[1]), "+f"(c[2]), "+f"(c[3])
        : "r"(a[0]), "r"(a[1]), "r"(a[2]), "r"(a[3]), "r"(b0), "r"(b1));
}

// load 128 rows x 128 bytes into smem tile (SW128 swizzled), cp.async
__device__ __forceinline__ void load_tile(u32 sbase, const char* gb) {
    int tid = threadIdx.x;
    #pragma unroll
    for (int i = 0; i < 4; i++) {
        int seg = i * 256 + tid;          // 1024 segments of 16B
        int r = seg >> 3, c = seg & 7;
        u32 off = (u32)(r * 128 + c * 16);
        off ^= (off >> 3) & 0x70;
        asm volatile("cp.async.cg.shared.global [%0], [%1], 16;"
                     :: "r"(sbase + off), "l"(gb + (size_t)r * 1024 + c * 16));
    }
}

template<int MODE>
__global__ __launch_bounds__(256)
void gemm_mma(const float* __restrict__ bias,
              const float* __restrict__ s0, const float* __restrict__ s1,
              const float* __restrict__ s2)
{
    extern __shared__ char dsm[];
    u32 base = (smem_u32(dsm) + 127u) & ~127u;

    const int tid = threadIdx.x;
    const int lane = tid & 31;
    const int wid = tid >> 5;
    const int warp_m = wid & 3;         // 0..3  -> m offset *32
    const int warp_n = wid >> 2;        // 0..1  -> n offset *64

    const int n0 = blockIdx.x * 128;
    const int m0 = blockIdx.y * 128;

    const __nv_bfloat16* Ap;
    const __nv_bfloat16* Wp;
    if constexpr (MODE == 0)      { Ap = g_a;   Wp = g_w + WOFF_QKV; }
    else if constexpr (MODE == 1) { Ap = g_ctx; Wp = g_w + WOFF_OUT; }
    else if constexpr (MODE == 2) { Ap = g_hh;  Wp = g_w + WOFF_W1; }
    else                          { Ap = g_h2;  Wp = g_w + WOFF_W2; }

    const char* Ab = (const char*)Ap + (size_t)m0 * 1024;
    const char* Wb = (const char*)Wp + (size_t)n0 * 1024;

    // chunk-pair schedule: hi*hi, hi*lo, lo*hi  (BK=64 bf16 = 128 B)
    const int a_idx[12] = {0,1,2,3, 0,1,2,3, 4,5,6,7};
    const int w_idx[12] = {0,1,2,3, 4,5,6,7, 0,1,2,3};

    float acc[2][8][4];
    #pragma unroll
    for (int i = 0; i < 2; i++)
        #pragma unroll
        for (int j = 0; j < 8; j++)
            #pragma unroll
            for (int q = 0; q < 4; q++) acc[i][j][q] = 0.f;

    const int a_mi = lane >> 3;
    const int a_row_base = ((a_mi & 1) << 3) + (lane & 7);
    const int a_kb_sel = (lane >> 4) << 4;
    const int b_row_base = ((a_mi >> 1) << 3) + (lane & 7);
    const int b_kb_sel = ((lane >> 3) & 1) << 4;

    load_tile(base, Ab + a_idx[0] * 128);
    load_tile(base + 16384, Wb + w_idx[0] * 128);
    asm volatile("cp.async.commit_group;");

    #pragma unroll
    for (int kc = 0; kc < 12; kc++) {
        const u32 st = (kc & 1) * 32768;
        if (kc + 1 < 12) {
            const u32 stn = ((kc + 1) & 1) * 32768;
            load_tile(base + stn, Ab + a_idx[kc + 1] * 128);
            load_tile(base + stn + 16384, Wb + w_idx[kc + 1] * 128);
            asm volatile("cp.async.commit_group;");
            asm volatile("cp.async.wait_group 1;");
        } else {
            asm volatile("cp.async.wait_group 0;");
        }
        __syncthreads();

        const u32 As = base + st;
        const u32 Bs = base + st + 16384;
        #pragma unroll
        for (int ks = 0; ks < 4; ks++) {
            u32 a[2][4];
            #pragma unroll
            for (int fm = 0; fm < 2; fm++) {
                int row = warp_m * 32 + fm * 16 + a_row_base;
                u32 kb = (u32)(ks * 32 + a_kb_sel);
                u32 ad = As + row * 128 + (kb ^ ((row & 7) << 4));
                ldsm4(ad, a[fm][0], a[fm][1], a[fm][2], a[fm][3]);
            }
            u32 b[4][4];
            #pragma unroll
            for (int fn = 0; fn < 4; fn++) {
                int row = warp_n * 64 + fn * 16 + b_row_base;
                u32 kb = (u32)(ks * 32 + b_kb_sel);
                u32 bd = Bs + row * 128 + (kb ^ ((row & 7) << 4));
                ldsm4(bd, b[fn][0], b[fn][1], b[fn][2], b[fn][3]);
            }
            #pragma unroll
            for (int fm = 0; fm < 2; fm++)
                #pragma unroll
                for (int f8 = 0; f8 < 8; f8++)
                    mma16816(acc[fm][f8], a[fm],
                             b[f8 >> 1][(f8 & 1) * 2], b[f8 >> 1][(f8 & 1) * 2 + 1]);
        }
        __syncthreads();
    }

    // ------------------------- epilogue -------------------------
    const int quad = lane >> 2, tq = lane & 3;
    #pragma unroll
    for (int fm = 0; fm < 2; fm++) {
        const int mA = m0 + warp_m * 32 + fm * 16 + quad;   // rows mA and mA+8
        const float* resA = nullptr; const float* resB = nullptr;
        if constexpr (MODE == 1) {
            int ba = mA / 3, ta = mA - ba * 3;
            resA = ((ta == 0) ? s0 : (ta == 1) ? s1 : s2) + (size_t)ba * 256;
            int mB = mA + 8;
            int bb = mB / 3, tb = mB - bb * 3;
            resB = ((tb == 0) ? s0 : (tb == 1) ? s1 : s2) + (size_t)bb * 256;
        }
        #pragma unroll
        for (int f8 = 0; f8 < 8; f8++) {
            const int n = n0 + warp_n * 64 + f8 * 8 + 2 * tq;
            float2 bv = *(const float2*)&bias[n];
            float v0 = acc[fm][f8][0] + bv.x;
            float v1 = acc[fm][f8][1] + bv.y;
            float v2 = acc[fm][f8][2] + bv.x;
            float v3 = acc[fm][f8][3] + bv.y;
            if constexpr (MODE == 0) {
                *(float2*)&g_qkv[(size_t)mA * 768 + n]       = {v0, v1};
                *(float2*)&g_qkv[(size_t)(mA + 8) * 768 + n] = {v2, v3};
            } else if constexpr (MODE == 1) {
                float2 r0 = *(const float2*)&resA[n];
                float2 r1 = *(const float2*)&resB[n];
                *(float2*)&g_x[(size_t)mA * 256 + n]       = {v0 + r0.x, v1 + r0.y};
                *(float2*)&g_x[(size_t)(mA + 8) * 256 + n] = {v2 + r1.x, v3 + r1.y};
            } else if constexpr (MODE == 2) {
                u32 h0, l0, h1, l1;
                split2(geluf(v0), geluf(v1), h0, l0);
                split2(geluf(v2), geluf(v3), h1, l1);
                *(u32*)&g_h2[(size_t)mA * 512 + n]             = h0;
                *(u32*)&g_h2[(size_t)mA * 512 + 256 + n]       = l0;
                *(u32*)&g_h2[(size_t)(mA + 8) * 512 + n]       = h1;
                *(u32*)&g_h2[(size_t)(mA + 8) * 512 + 256 + n] = l1;
            } else {
                *(float2*)&g_h3[(size_t)mA * 128 + n]       = {geluf(v0), geluf(v1)};
                *(float2*)&g_h3[(size_t)(mA + 8) * 128 + n] = {geluf(v2), geluf(v3)};
            }
        }
    }
}

// ---------------------------------------------------------------------------
// attention: warp per batch row; writes ctx as split bf16 [3B, 512]
// ---------------------------------------------------------------------------
__global__ __launch_bounds__(256)
void attn_k(int B)
{
    int warp = threadIdx.x >> 5, lane = threadIdx.x & 31;
    int b = blockIdx.x * 8 + warp;
    if (b >= B) return;
    size_t base = (size_t)b * 3 * 768;
    int d0 = lane * 8;

    float q[3][8], k[3][8], v[3][8];
    #pragma unroll
    for (int t = 0; t < 3; t++) {
        const float* row = g_qkv + base + (size_t)t * 768;
        *(float4*)&q[t][0] = *(const float4*)(row + d0);
        *(float4*)&q[t][4] = *(const float4*)(row + d0 + 4);
        *(float4*)&k[t][0] = *(const float4*)(row + 256 + d0);
        *(float4*)&k[t][4] = *(const float4*)(row + 256 + d0 + 4);
        *(float4*)&v[t][0] = *(const float4*)(row + 512 + d0);
        *(float4*)&v[t][4] = *(const float4*)(row + 512 + d0 + 4);
    }
    float s[3][3];
    #pragma unroll
    for (int t = 0; t < 3; t++)
        #pragma unroll
        for (int u = 0; u < 3; u++) {
            float p = 0.f;
            #pragma unroll
            for (int j = 0; j < 8; j++) p += q[t][j] * k[u][j];
            p += __shfl_xor_sync(0xffffffffu, p, 1);
            p += __shfl_xor_sync(0xffffffffu, p, 2);
            p += __shfl_xor_sync(0xffffffffu, p, 4);
            s[t][u] = p * 0.125f;
        }
    #pragma unroll
    for (int t = 0; t < 3; t++) {
        float mx = fmaxf(s[t][0], fmaxf(s[t][1], s[t][2]));
        float e0 = expf(s[t][0] - mx);
        float e1 = expf(s[t][1] - mx);
        float e2 = expf(s[t][2] - mx);
        float inv = 1.f / (e0 + e1 + e2);
        u32 hi[4], lo[4];
        #pragma unroll
        for (int j = 0; j < 8; j += 2) {
            float c0 = (e0 * v[0][j]   + e1 * v[1][j]   + e2 * v[2][j])   * inv;
            float c1 = (e0 * v[0][j+1] + e1 * v[1][j+1] + e2 * v[2][j+1]) * inv;
            split2(c0, c1, hi[j >> 1], lo[j >> 1]);
        }
        __nv_bfloat16* crow = g_ctx + ((size_t)b * 3 + t) * 512 + d0;
        *(uint4*)crow         = *(uint4*)hi;
        *(uint4*)(crow + 256) = *(uint4*)lo;
    }
}

// ---------------------------------------------------------------------------
// fuse: LN1 per token, gate softmax, fused (fp32), LN2 -> g_hh (split)
// ---------------------------------------------------------------------------
__global__ __launch_bounds__(256)
void fuse_k(const float* __restrict__ s0, const float* __restrict__ s1,
            const float* __restrict__ s2,
            const float* __restrict__ ln1g, const float* __restrict__ ln1b,
            const float* __restrict__ gw,   const float* __restrict__ gb,
            const float* __restrict__ ln2g, const float* __restrict__ ln2b,
            float* __restrict__ out_fused, int B)
{
    int warp = threadIdx.x >> 5, lane = threadIdx.x & 31;
    int b = blockIdx.x * 8 + warp;
    if (b >= B) return;
    int d0 = lane * 8;
    const float* srcs[3] = {s0, s1, s2};

    float y[3][8];
    float gpart[3] = {0.f, 0.f, 0.f};
    #pragma unroll
    for (int t = 0; t < 3; t++) {
        float x[8];
        const float* row = g_x + ((size_t)b * 3 + t) * 256;
        *(float4*)&x[0] = *(const float4*)(row + d0);
        *(float4*)&x[4] = *(const float4*)(row + d0 + 4);
        float s = 0.f;
        #pragma unroll
        for (int j = 0; j < 8; j++) s += x[j];
        s = wsum(s);
        float mu = s * (1.f / 256.f);
        float vv = 0.f;
        #pragma unroll
        for (int j = 0; j < 8; j++) { float d = x[j] - mu; vv += d * d; }
        vv = wsum(vv);
        float rs = rsqrtf(vv * (1.f / 256.f) + 1e-5f);
        float4 ga = *(const float4*)(ln1g + d0), gb4 = *(const float4*)(ln1g + d0 + 4);
        float4 ba = *(const float4*)(ln1b + d0), bb4 = *(const float4*)(ln1b + d0 + 4);
        const float gg[8] = {ga.x, ga.y, ga.z, ga.w, gb4.x, gb4.y, gb4.z, gb4.w};
        const float bb[8] = {ba.x, ba.y, ba.z, ba.w, bb4.x, bb4.y, bb4.z, bb4.w};
        #pragma unroll
        for (int j = 0; j < 8; j++)
            y[t][j] = (x[j] - mu) * rs * gg[j] + bb[j];

        float iv[8];
        const float* in = srcs[t] + (size_t)b * 256;
        *(float4*)&iv[0] = *(const float4*)(in + d0);
        *(float4*)&iv[4] = *(const float4*)(in + d0 + 4);
        #pragma unroll
        for (int g = 0; g < 3; g++) {
            const float* wrow = gw + (size_t)g * 768 + t * 256 + d0;
            float4 wa = *(const float4*)wrow;
            float4 wb = *(const float4*)(wrow + 4);
            gpart[g] += iv[0] * wa.x + iv[1] * wa.y + iv[2] * wa.z + iv[3] * wa.w
                      + iv[4] * wb.x + iv[5] * wb.y + iv[6] * wb.z + iv[7] * wb.w;
        }
    }
    float gl[3];
    #pragma unroll
    for (int g = 0; g < 3; g++) gl[g] = wsum(gpart[g]) + gb[g];
    float mx = fmaxf(gl[0], fmaxf(gl[1], gl[2]));
    float e0 = expf(gl[0] - mx), e1 = expf(gl[1] - mx), e2 = expf(gl[2] - mx);
    float inv = 1.f / (e0 + e1 + e2);
    float w0 = e0 * inv, w1 = e1 * inv, w2 = e2 * inv;

    float f[8];
    #pragma unroll
    for (int j = 0; j < 8; j++)
        f[j] = w0 * y[0][j] + w1 * y[1][j] + w2 * y[2][j];
    if (out_fused) {
        float* orow = out_fused + (size_t)b * 256 + d0;
        *(float4*)orow       = *(float4*)&f[0];
        *(float4*)(orow + 4) = *(float4*)&f[4];
    }
    float s2v = 0.f;
    #pragma unroll
    for (int j = 0; j < 8; j++) s2v += f[j];
    s2v = wsum(s2v);
    float mu2 = s2v * (1.f / 256.f);
    float vv2 = 0.f;
    #pragma unroll
    for (int j = 0; j < 8; j++) { float d = f[j] - mu2; vv2 += d * d; }
    vv2 = wsum(vv2);
    float rs2 = rsqrtf(vv2 * (1.f / 256.f) + 1e-5f);
    u32 hi[4], lo[4];
    #pragma unroll
    for (int j = 0; j < 8; j += 2) {
        float h0 = (f[j]   - mu2) * rs2 * ln2g[d0 + j]   + ln2b[d0 + j];
        float h1 = (f[j+1] - mu2) * rs2 * ln2g[d0 + j+1] + ln2b[d0 + j+1];
        split2(h0, h1, hi[j >> 1], lo[j >> 1]);
    }
    __nv_bfloat16* hrow = g_hh + (size_t)b * 512 + d0;
    *(uint4*)hrow         = *(uint4*)hi;
    *(uint4*)(hrow + 256) = *(uint4*)lo;
}

// ---------------------------------------------------------------------------
// logits = h3 @ w3^T + b3
// ---------------------------------------------------------------------------
__global__ __launch_bounds__(256)
void logit_k(const float* __restrict__ w3, const float* __restrict__ b3,
             float* __restrict__ out, int B)
{
    int warp = threadIdx.x >> 5, lane = threadIdx.x & 31;
    int b = blockIdx.x * 8 + warp;
    if (b >= B) return;
    int d0 = lane * 4;
    float4 h = *(const float4*)(g_h3 + (size_t)b * 128 + d0);
    float r[7];
    #pragma unroll
    for (int j = 0; j < 7; j++) {
        float4 w = *(const float4*)(w3 + j * 128 + d0);
        float p = h.x * w.x + h.y * w.y + h.z * w.z + h.w * w.w;
        r[j] = wsum(p);
    }
    if (lane == 0) {
        #pragma unroll
        for (int j = 0; j < 7; j++) out[(size_t)b * 7 + j] = r[j] + b3[j];
    }
}

// ---------------------------------------------------------------------------
extern "C" void kernel_launch(void* const* d_in, const int* in_sizes, int n_in,
                              void* d_out, int out_size)
{
    const float* f_swin    = (const float*)d_in[0];
    const float* f_maxvit  = (const float*)d_in[1];
    const float* f_focal   = (const float*)d_in[2];
    const float* in_proj_w = (const float*)d_in[3];
    const float* in_proj_b = (const float*)d_in[4];
    const float* out_w  = (const float*)d_in[5];
    const float* out_b  = (const float*)d_in[6];
    const float* ln1_g  = (const float*)d_in[7];
    const float* ln1_b  = (const float*)d_in[8];
    const float* gate_w = (const float*)d_in[9];
    const float* gate_b = (const float*)d_in[10];
    const float* ln2_g  = (const float*)d_in[11];
    const float* ln2_b  = (const float*)d_in[12];
    const float* w1 = (const float*)d_in[13];
    const float* b1 = (const float*)d_in[14];
    const float* w2 = (const float*)d_in[15];
    const float* b2 = (const float*)d_in[16];
    const float* w3 = (const float*)d_in[17];
    const float* b3 = (const float*)d_in[18];

    int B = in_sizes[0] / 256;
    if (B > BMAX) B = BMAX;
    int rows3 = 3 * B;

    float* outp = (float*)d_out;
    float* out_logits = outp;
    float* out_fused = (out_size >= B * 263) ? (outp + (size_t)B * 7) : nullptr;

    const int SMEM = 2 * 32768 + 256;
    cudaFuncSetAttribute(gemm_mma<0>, cudaFuncAttributeMaxDynamicSharedMemorySize, SMEM);
    cudaFuncSetAttribute(gemm_mma<1>, cudaFuncAttributeMaxDynamicSharedMemorySize, SMEM);
    cudaFuncSetAttribute(gemm_mma<2>, cudaFuncAttributeMaxDynamicSharedMemorySize, SMEM);
    cudaFuncSetAttribute(gemm_mma<3>, cudaFuncAttributeMaxDynamicSharedMemorySize, SMEM);

    dim3 blk(256);

    // converts
    conv_feat_k<<<(rows3 * 64 + 255) / 256, blk>>>(f_swin, f_maxvit, f_focal, rows3);
    conv_w_k<<<(768 * 64 + 255) / 256, blk>>>(in_proj_w, 768, WOFF_QKV);
    conv_w_k<<<(256 * 64 + 255) / 256, blk>>>(out_w, 256, WOFF_OUT);
    conv_w_k<<<(256 * 64 + 255) / 256, blk>>>(w1, 256, WOFF_W1);
    conv_w_k<<<(128 * 64 + 255) / 256, blk>>>(w2, 128, WOFF_W2);

    // qkv GEMM [3B, 768]
    gemm_mma<0><<<dim3(6, rows3 / 128), blk, SMEM>>>(in_proj_b, nullptr, nullptr, nullptr);
    // attention
    attn_k<<<(B + 7) / 8, blk>>>(B);
    // out-proj + residual [3B, 256]
    gemm_mma<1><<<dim3(2, rows3 / 128), blk, SMEM>>>(out_b, f_swin, f_maxvit, f_focal);
    // LN1 + gate + fused + LN2
    fuse_k<<<(B + 7) / 8, blk>>>(f_swin, f_maxvit, f_focal,
                                 ln1_g, ln1_b, gate_w, gate_b, ln2_g, ln2_b,
                                 out_fused, B);
    // deep head
    gemm_mma<2><<<dim3(2, B / 128), blk, SMEM>>>(b1, nullptr, nullptr, nullptr);
    gemm_mma<3><<<dim3(1, B / 128), blk, SMEM>>>(b2, nullptr, nullptr, nullptr);
    logit_k<<<(B + 7) / 8, blk>>>(w3, b3, out_logits, B);
}

// round 5
// speedup vs baseline: 3.2060x; 1.2883x over previous
#include <cuda_runtime.h>
#include <cuda_bf16.h>
#include <math.h>
#include <stdint.h>

typedef unsigned int u32;
typedef unsigned long long u64;

#define BMAX 65536

// ---------------------------------------------------------------------------
// Device scratch.
//  g_a   : features bf16 single      [3B, 256]
//  g_qkv : qkv bf16                  [3B, 768]
//  g_ctx : attention ctx bf16 single [3B, 256]
//  g_x   : att_out + residual fp32   [3B, 256]
//  g_hh  : LN2(fused) split bf16     [B, 512]  (hi | lo)
//  g_h2  : GELU(h@w1) split bf16     [B, 512]
//  g_h3  : GELU(h2@w2) fp32          [B, 128]
//  g_w   : split weights             [N, 512] each
// ---------------------------------------------------------------------------
__device__ __nv_bfloat16 g_a  [(size_t)BMAX * 3 * 256];
__device__ __nv_bfloat16 g_qkv[(size_t)BMAX * 3 * 768];
__device__ __nv_bfloat16 g_ctx[(size_t)BMAX * 3 * 256];
__device__ float         g_x  [(size_t)BMAX * 3 * 256];
__device__ __nv_bfloat16 g_hh [(size_t)BMAX * 512];
__device__ __nv_bfloat16 g_h2 [(size_t)BMAX * 512];
__device__ float         g_h3 [(size_t)BMAX * 128];
__device__ __nv_bfloat16 g_w  [(size_t)(768 + 256 + 256 + 128) * 512];

#define WOFF_QKV 0
#define WOFF_OUT (768 * 512)
#define WOFF_W1  ((768 + 256) * 512)
#define WOFF_W2  ((768 + 512) * 512)

__device__ __forceinline__ u32 smem_u32(const void* p) {
    u32 a;
    asm("{ .reg .u64 t; cvta.to.shared.u64 t, %1; cvt.u32.u64 %0, t; }" : "=r"(a) : "l"(p));
    return a;
}
__device__ __forceinline__ float geluf(float x) {
    return 0.5f * x * (1.0f + erff(x * 0.7071067811865476f));
}
__device__ __forceinline__ float wsum(float v) {
    #pragma unroll
    for (int o = 16; o > 0; o >>= 1) v += __shfl_xor_sync(0xffffffffu, v, o);
    return v;
}
__device__ __forceinline__ u32 bf2bits(__nv_bfloat162 h) {
    return *reinterpret_cast<u32*>(&h);
}
// split fp32 pair into (hi, lo) bf16x2 words
__device__ __forceinline__ void split2(float a, float b, u32& h, u32& l) {
    __nv_bfloat162 hh = __floats2bfloat162_rn(a, b);
    float ra = a - __bfloat162float(hh.x);
    float rb = b - __bfloat162float(hh.y);
    __nv_bfloat162 ll = __floats2bfloat162_rn(ra, rb);
    h = bf2bits(hh);
    l = bf2bits(ll);
}

// ---------------------------------------------------------------------------
// conv_feat: fp32 features -> bf16 single [3B, 256] (token-interleaved)
// ---------------------------------------------------------------------------
__global__ __launch_bounds__(256)
void conv_feat_k(const float* __restrict__ s0, const float* __restrict__ s1,
                 const float* __restrict__ s2, int rows3)
{
    int id = blockIdx.x * 256 + threadIdx.x;
    if (id >= rows3 * 64) return;
    int row = id >> 6;
    int k = (id & 63) << 2;
    int b = row / 3, t = row - b * 3;
    const float* s = (t == 0) ? s0 : (t == 1) ? s1 : s2;
    float4 v = *(const float4*)(s + (size_t)b * 256 + k);
    u32* p = (u32*)&g_a[(size_t)row * 256 + k];
    p[0] = bf2bits(__floats2bfloat162_rn(v.x, v.y));
    p[1] = bf2bits(__floats2bfloat162_rn(v.z, v.w));
}

// conv_w: fp32 [rows,256] -> split bf16 [rows,512]
__global__ __launch_bounds__(256)
void conv_w_k(const float* __restrict__ src, int rows, int woff)
{
    int id = blockIdx.x * 256 + threadIdx.x;
    if (id >= rows * 64) return;
    int row = id >> 6;
    int k = (id & 63) << 2;
    float4 v = *(const float4*)(src + (size_t)row * 256 + k);
    u32 h0, l0, h1, l1;
    split2(v.x, v.y, h0, l0);
    split2(v.z, v.w, h1, l1);
    __nv_bfloat16* dst = g_w + (size_t)woff + (size_t)row * 512;
    u32* hp = (u32*)(dst + k);
    u32* lp = (u32*)(dst + 256 + k);
    hp[0] = h0; hp[1] = h1;
    lp[0] = l0; lp[1] = l1;
}

// ---------------------------------------------------------------------------
// mma.sync bf16 GEMM, resident-A / streamed-W.
// MODE 0: A=g_a single (4 ch), NP=8 : qkv bf16, +bias        -> g_qkv (ldc 768)
// MODE 1: A=g_ctx single (4 ch), NP=8 : +bias +residual fp32 -> g_x   (ldc 256)
// MODE 2: A=g_hh split (8 ch), NP=12 : +bias GELU split bf16 -> g_h2
// MODE 3: A=g_h2 split (8 ch), NP=12 : +bias GELU fp32       -> g_h3 (ldc 128)
// chunk-pair schedule (split): hi*hi then hi*lo then lo*hi.
// ---------------------------------------------------------------------------
__device__ __forceinline__ void ldsm4(u32 addr, u32& r0, u32& r1, u32& r2, u32& r3) {
    asm volatile("ldmatrix.sync.aligned.m8n8.x4.shared.b16 {%0,%1,%2,%3}, [%4];"
                 : "=r"(r0), "=r"(r1), "=r"(r2), "=r"(r3) : "r"(addr));
}
__device__ __forceinline__ void mma16816(float* c, const u32* a, u32 b0, u32 b1) {
    asm volatile(
        "mma.sync.aligned.m16n8k16.row.col.f32.bf16.bf16.f32 "
        "{%0,%1,%2,%3}, {%4,%5,%6,%7}, {%8,%9}, {%0,%1,%2,%3};"
        : "+f"(c[0]), "+f"(c[1]), "+f"(c[2]), "+f"(c[3])
        : "r"(a[0]), "r"(a[1]), "r"(a[2]), "r"(a[3]), "r"(b0), "r"(b1));
}

// load 128 rows x 128 bytes (one K-chunk) into SW128-swizzled smem tile
template<int ROWB>
__device__ __forceinline__ void load_tile(u32 sbase, const char* gb) {
    int tid = threadIdx.x;
    #pragma unroll
    for (int i = 0; i < 4; i++) {
        int seg = i * 256 + tid;          // 1024 segments of 16B
        int r = seg >> 3, c = seg & 7;
        u32 off = (u32)(r * 128 + c * 16);
        off ^= (off >> 3) & 0x70;
        asm volatile("cp.async.cg.shared.global [%0], [%1], 16;"
                     :: "r"(sbase + off), "l"(gb + (size_t)r * ROWB + c * 16));
    }
}

template<int MODE>
__global__ __launch_bounds__(256)
void gemm_mma(const float* __restrict__ bias,
              const float* __restrict__ s0, const float* __restrict__ s1,
              const float* __restrict__ s2)
{
    constexpr int NP   = (MODE <= 1) ? 8 : 12;
    constexpr int NCHA = (MODE <= 1) ? 4 : 8;
    constexpr int AROW = (MODE <= 1) ? 512 : 1024;   // bytes per A row

    extern __shared__ char dsm[];
    u32 base = (smem_u32(dsm) + 1023u) & ~1023u;
    const u32 wbase = base + NCHA * 16384;

    const int tid = threadIdx.x;
    const int lane = tid & 31;
    const int wid = tid >> 5;
    const int warp_m = wid & 3;
    const int warp_n = wid >> 2;

    const int n0 = blockIdx.x * 128;
    const int m0 = blockIdx.y * 128;

    const __nv_bfloat16* Ap;
    const __nv_bfloat16* Wp;
    if constexpr (MODE == 0)      { Ap = g_a;   Wp = g_w + WOFF_QKV; }
    else if constexpr (MODE == 1) { Ap = g_ctx; Wp = g_w + WOFF_OUT; }
    else if constexpr (MODE == 2) { Ap = g_hh;  Wp = g_w + WOFF_W1; }
    else                          { Ap = g_h2;  Wp = g_w + WOFF_W2; }

    const char* Ab = (const char*)Ap + (size_t)m0 * AROW;
    const char* Wb = (const char*)Wp + (size_t)n0 * 1024;

    // chunk schedules
    const int a_idx12[12] = {0,1,2,3, 0,1,2,3, 4,5,6,7};
    const int w_idx12[12] = {0,1,2,3, 4,5,6,7, 0,1,2,3};

    float acc[2][8][4];
    #pragma unroll
    for (int i = 0; i < 2; i++)
        #pragma unroll
        for (int j = 0; j < 8; j++)
            #pragma unroll
            for (int q = 0; q < 4; q++) acc[i][j][q] = 0.f;

    const int a_mi = lane >> 3;
    const int a_row_base = ((a_mi & 1) << 3) + (lane & 7);
    const int a_kb_sel = (lane >> 4) << 4;
    const int b_row_base = ((a_mi >> 1) << 3) + (lane & 7);
    const int b_kb_sel = ((lane >> 3) & 1) << 4;

    // resident A chunks (one commit group)
    #pragma unroll
    for (int c = 0; c < NCHA; c++)
        load_tile<AROW>(base + c * 16384, Ab + c * 128);
    asm volatile("cp.async.commit_group;");
    // W prologue
    load_tile<1024>(wbase, Wb + 0 * 128);   // w_idx[0] == 0 in all schedules
    asm volatile("cp.async.commit_group;");

    #pragma unroll
    for (int kc = 0; kc < NP; kc++) {
        const int ai = (MODE <= 1) ? (kc & 3) : a_idx12[kc];
        if (kc + 1 < NP) {
            const int wi = (MODE <= 1) ? (kc + 1) : w_idx12[kc + 1];
            load_tile<1024>(wbase + ((kc + 1) & 1) * 16384, Wb + wi * 128);
            asm volatile("cp.async.commit_group;");
            asm volatile("cp.async.wait_group 1;");
        } else {
            asm volatile("cp.async.wait_group 0;");
        }
        __syncthreads();

        const u32 As = base + ai * 16384;
        const u32 Bs = wbase + (kc & 1) * 16384;
        #pragma unroll
        for (int ks = 0; ks < 4; ks++) {
            u32 a[2][4];
            #pragma unroll
            for (int fm = 0; fm < 2; fm++) {
                int row = warp_m * 32 + fm * 16 + a_row_base;
                u32 kb = (u32)(ks * 32 + a_kb_sel);
                u32 ad = As + row * 128 + (kb ^ ((row & 7) << 4));
                ldsm4(ad, a[fm][0], a[fm][1], a[fm][2], a[fm][3]);
            }
            u32 b[4][4];
            #pragma unroll
            for (int fn = 0; fn < 4; fn++) {
                int row = warp_n * 64 + fn * 16 + b_row_base;
                u32 kb = (u32)(ks * 32 + b_kb_sel);
                u32 bd = Bs + row * 128 + (kb ^ ((row & 7) << 4));
                ldsm4(bd, b[fn][0], b[fn][1], b[fn][2], b[fn][3]);
            }
            #pragma unroll
            for (int fm = 0; fm < 2; fm++)
                #pragma unroll
                for (int f8 = 0; f8 < 8; f8++)
                    mma16816(acc[fm][f8], a[fm],
                             b[f8 >> 1][(f8 & 1) * 2], b[f8 >> 1][(f8 & 1) * 2 + 1]);
        }
        __syncthreads();
    }

    // ------------------------- epilogue -------------------------
    const int quad = lane >> 2, tq = lane & 3;
    #pragma unroll
    for (int fm = 0; fm < 2; fm++) {
        const int mA = m0 + warp_m * 32 + fm * 16 + quad;   // rows mA and mA+8
        const float* resA = nullptr; const float* resB = nullptr;
        if constexpr (MODE == 1) {
            int ba = mA / 3, ta = mA - ba * 3;
            resA = ((ta == 0) ? s0 : (ta == 1) ? s1 : s2) + (size_t)ba * 256;
            int mB = mA + 8;
            int bb = mB / 3, tb = mB - bb * 3;
            resB = ((tb == 0) ? s0 : (tb == 1) ? s1 : s2) + (size_t)bb * 256;
        }
        #pragma unroll
        for (int f8 = 0; f8 < 8; f8++) {
            const int n = n0 + warp_n * 64 + f8 * 8 + 2 * tq;
            float2 bv = *(const float2*)&bias[n];
            float v0 = acc[fm][f8][0] + bv.x;
            float v1 = acc[fm][f8][1] + bv.y;
            float v2 = acc[fm][f8][2] + bv.x;
            float v3 = acc[fm][f8][3] + bv.y;
            if constexpr (MODE == 0) {
                *(u32*)&g_qkv[(size_t)mA * 768 + n]       = bf2bits(__floats2bfloat162_rn(v0, v1));
                *(u32*)&g_qkv[(size_t)(mA + 8) * 768 + n] = bf2bits(__floats2bfloat162_rn(v2, v3));
            } else if constexpr (MODE == 1) {
                float2 r0 = *(const float2*)&resA[n];
                float2 r1 = *(const float2*)&resB[n];
                *(float2*)&g_x[(size_t)mA * 256 + n]       = {v0 + r0.x, v1 + r0.y};
                *(float2*)&g_x[(size_t)(mA + 8) * 256 + n] = {v2 + r1.x, v3 + r1.y};
            } else if constexpr (MODE == 2) {
                u32 h0, l0, h1, l1;
                split2(geluf(v0), geluf(v1), h0, l0);
                split2(geluf(v2), geluf(v3), h1, l1);
                *(u32*)&g_h2[(size_t)mA * 512 + n]             = h0;
                *(u32*)&g_h2[(size_t)mA * 512 + 256 + n]       = l0;
                *(u32*)&g_h2[(size_t)(mA + 8) * 512 + n]       = h1;
                *(u32*)&g_h2[(size_t)(mA + 8) * 512 + 256 + n] = l1;
            } else {
                *(float2*)&g_h3[(size_t)mA * 128 + n]       = {geluf(v0), geluf(v1)};
                *(float2*)&g_h3[(size_t)(mA + 8) * 128 + n] = {geluf(v2), geluf(v3)};
            }
        }
    }
}

// ---------------------------------------------------------------------------
// attention: warp per token; reads bf16 qkv, writes ctx bf16 single
// ---------------------------------------------------------------------------
__global__ __launch_bounds__(256)
void attn_k(int B)
{
    int warp = threadIdx.x >> 5, lane = threadIdx.x & 31;
    int b = blockIdx.x * 8 + warp;
    if (b >= B) return;
    int d0 = lane * 8;

    float q[3][8], k[3][8], v[3][8];
    #pragma unroll
    for (int t = 0; t < 3; t++) {
        const __nv_bfloat16* row = g_qkv + ((size_t)b * 3 + t) * 768;
        uint4 qr = *(const uint4*)(row + d0);
        uint4 kr = *(const uint4*)(row + 256 + d0);
        uint4 vr = *(const uint4*)(row + 512 + d0);
        const u32* qw = (const u32*)&qr;
        const u32* kw = (const u32*)&kr;
        const u32* vw = (const u32*)&vr;
        #pragma unroll
        for (int j = 0; j < 4; j++) {
            float2 qf = __bfloat1622float2(*(const __nv_bfloat162*)&qw[j]);
            float2 kf = __bfloat1622float2(*(const __nv_bfloat162*)&kw[j]);
            float2 vf = __bfloat1622float2(*(const __nv_bfloat162*)&vw[j]);
            q[t][2*j] = qf.x; q[t][2*j+1] = qf.y;
            k[t][2*j] = kf.x; k[t][2*j+1] = kf.y;
            v[t][2*j] = vf.x; v[t][2*j+1] = vf.y;
        }
    }
    float s[3][3];
    #pragma unroll
    for (int t = 0; t < 3; t++)
        #pragma unroll
        for (int u = 0; u < 3; u++) {
            float p = 0.f;
            #pragma unroll
            for (int j = 0; j < 8; j++) p += q[t][j] * k[u][j];
            p += __shfl_xor_sync(0xffffffffu, p, 1);
            p += __shfl_xor_sync(0xffffffffu, p, 2);
            p += __shfl_xor_sync(0xffffffffu, p, 4);
            s[t][u] = p * 0.125f;
        }
    #pragma unroll
    for (int t = 0; t < 3; t++) {
        float mx = fmaxf(s[t][0], fmaxf(s[t][1], s[t][2]));
        float e0 = expf(s[t][0] - mx);
        float e1 = expf(s[t][1] - mx);
        float e2 = expf(s[t][2] - mx);
        float inv = 1.f / (e0 + e1 + e2);
        u32 cw[4];
        #pragma unroll
        for (int j = 0; j < 8; j += 2) {
            float c0 = (e0 * v[0][j]   + e1 * v[1][j]   + e2 * v[2][j])   * inv;
            float c1 = (e0 * v[0][j+1] + e1 * v[1][j+1] + e2 * v[2][j+1]) * inv;
            cw[j >> 1] = bf2bits(__floats2bfloat162_rn(c0, c1));
        }
        *(uint4*)(g_ctx + ((size_t)b * 3 + t) * 256 + d0) = *(uint4*)cw;
    }
}

// ---------------------------------------------------------------------------
// fuse: LN1 per token, gate softmax, fused (fp32), LN2 -> g_hh (split).
// Params cached in smem; grid-stride over tokens.
// ---------------------------------------------------------------------------
__global__ __launch_bounds__(256)
void fuse_k(const float* __restrict__ s0, const float* __restrict__ s1,
            const float* __restrict__ s2,
            const float* __restrict__ ln1g, const float* __restrict__ ln1b,
            const float* __restrict__ gw,   const float* __restrict__ gb,
            const float* __restrict__ ln2g, const float* __restrict__ ln2b,
            float* __restrict__ out_fused, int B)
{
    __shared__ float s_gw[2304];
    __shared__ float s_ln[1024];
    for (int i = threadIdx.x; i < 2304; i += 256) s_gw[i] = gw[i];
    if (threadIdx.x < 256) {
        int i = threadIdx.x;
        s_ln[i]       = ln1g[i];
        s_ln[256 + i] = ln1b[i];
        s_ln[512 + i] = ln2g[i];
        s_ln[768 + i] = ln2b[i];
    }
    __syncthreads();

    int warp = threadIdx.x >> 5, lane = threadIdx.x & 31;
    int d0 = lane * 8;
    const float* srcs[3] = {s0, s1, s2};

    for (int b = blockIdx.x * 8 + warp; b < B; b += gridDim.x * 8) {
        float y[3][8];
        float gpart[3] = {0.f, 0.f, 0.f};
        #pragma unroll
        for (int t = 0; t < 3; t++) {
            float x[8];
            const float* row = g_x + ((size_t)b * 3 + t) * 256;
            *(float4*)&x[0] = *(const float4*)(row + d0);
            *(float4*)&x[4] = *(const float4*)(row + d0 + 4);
            float s = 0.f;
            #pragma unroll
            for (int j = 0; j < 8; j++) s += x[j];
            s = wsum(s);
            float mu = s * (1.f / 256.f);
            float vv = 0.f;
            #pragma unroll
            for (int j = 0; j < 8; j++) { float d = x[j] - mu; vv += d * d; }
            vv = wsum(vv);
            float rs = rsqrtf(vv * (1.f / 256.f) + 1e-5f);
            #pragma unroll
            for (int j = 0; j < 8; j++)
                y[t][j] = (x[j] - mu) * rs * s_ln[d0 + j] + s_ln[256 + d0 + j];

            float iv[8];
            const float* in = srcs[t] + (size_t)b * 256;
            *(float4*)&iv[0] = *(const float4*)(in + d0);
            *(float4*)&iv[4] = *(const float4*)(in + d0 + 4);
            #pragma unroll
            for (int g = 0; g < 3; g++) {
                const float* wrow = s_gw + g * 768 + t * 256 + d0;
                #pragma unroll
                for (int j = 0; j < 8; j++) gpart[g] += iv[j] * wrow[j];
            }
        }
        float gl[3];
        #pragma unroll
        for (int g = 0; g < 3; g++) gl[g] = wsum(gpart[g]) + gb[g];
        float mx = fmaxf(gl[0], fmaxf(gl[1], gl[2]));
        float e0 = expf(gl[0] - mx), e1 = expf(gl[1] - mx), e2 = expf(gl[2] - mx);
        float inv = 1.f / (e0 + e1 + e2);
        float w0 = e0 * inv, w1 = e1 * inv, w2 = e2 * inv;

        float f[8];
        #pragma unroll
        for (int j = 0; j < 8; j++)
            f[j] = w0 * y[0][j] + w1 * y[1][j] + w2 * y[2][j];
        if (out_fused) {
            float* orow = out_fused + (size_t)b * 256 + d0;
            *(float4*)orow       = *(float4*)&f[0];
            *(float4*)(orow + 4) = *(float4*)&f[4];
        }
        float s2v = 0.f;
        #pragma unroll
        for (int j = 0; j < 8; j++) s2v += f[j];
        s2v = wsum(s2v);
        float mu2 = s2v * (1.f / 256.f);
        float vv2 = 0.f;
        #pragma unroll
        for (int j = 0; j < 8; j++) { float d = f[j] - mu2; vv2 += d * d; }
        vv2 = wsum(vv2);
        float rs2 = rsqrtf(vv2 * (1.f / 256.f) + 1e-5f);
        u32 hi[4], lo[4];
        #pragma unroll
        for (int j = 0; j < 8; j += 2) {
            float h0 = (f[j]   - mu2) * rs2 * s_ln[512 + d0 + j]   + s_ln[768 + d0 + j];
            float h1 = (f[j+1] - mu2) * rs2 * s_ln[512 + d0 + j+1] + s_ln[768 + d0 + j+1];
            split2(h0, h1, hi[j >> 1], lo[j >> 1]);
        }
        __nv_bfloat16* hrow = g_hh + (size_t)b * 512 + d0;
        *(uint4*)hrow         = *(uint4*)hi;
        *(uint4*)(hrow + 256) = *(uint4*)lo;
    }
}

// ---------------------------------------------------------------------------
// logits = h3 @ w3^T + b3
// ---------------------------------------------------------------------------
__global__ __launch_bounds__(256)
void logit_k(const float* __restrict__ w3, const float* __restrict__ b3,
             float* __restrict__ out, int B)
{
    int warp = threadIdx.x >> 5, lane = threadIdx.x & 31;
    int b = blockIdx.x * 8 + warp;
    if (b >= B) return;
    int d0 = lane * 4;
    float4 h = *(const float4*)(g_h3 + (size_t)b * 128 + d0);
    float r[7];
    #pragma unroll
    for (int j = 0; j < 7; j++) {
        float4 w = *(const float4*)(w3 + j * 128 + d0);
        float p = h.x * w.x + h.y * w.y + h.z * w.z + h.w * w.w;
        r[j] = wsum(p);
    }
    if (lane == 0) {
        #pragma unroll
        for (int j = 0; j < 7; j++) out[(size_t)b * 7 + j] = r[j] + b3[j];
    }
}

// ---------------------------------------------------------------------------
extern "C" void kernel_launch(void* const* d_in, const int* in_sizes, int n_in,
                              void* d_out, int out_size)
{
    const float* f_swin    = (const float*)d_in[0];
    const float* f_maxvit  = (const float*)d_in[1];
    const float* f_focal   = (const float*)d_in[2];
    const float* in_proj_w = (const float*)d_in[3];
    const float* in_proj_b = (const float*)d_in[4];
    const float* out_w  = (const float*)d_in[5];
    const float* out_b  = (const float*)d_in[6];
    const float* ln1_g  = (const float*)d_in[7];
    const float* ln1_b  = (const float*)d_in[8];
    const float* gate_w = (const float*)d_in[9];
    const float* gate_b = (const float*)d_in[10];
    const float* ln2_g  = (const float*)d_in[11];
    const float* ln2_b  = (const float*)d_in[12];
    const float* w1 = (const float*)d_in[13];
    const float* b1 = (const float*)d_in[14];
    const float* w2 = (const float*)d_in[15];
    const float* b2 = (const float*)d_in[16];
    const float* w3 = (const float*)d_in[17];
    const float* b3 = (const float*)d_in[18];

    int B = in_sizes[0] / 256;
    if (B > BMAX) B = BMAX;
    int rows3 = 3 * B;

    float* outp = (float*)d_out;
    float* out_logits = outp;
    float* out_fused = (out_size >= B * 263) ? (outp + (size_t)B * 7) : nullptr;

    const int SMEM01 = 4 * 16384 + 2 * 16384 + 1024;   // 99 KB
    const int SMEM23 = 8 * 16384 + 2 * 16384 + 1024;   // 165 KB
    cudaFuncSetAttribute(gemm_mma<0>, cudaFuncAttributeMaxDynamicSharedMemorySize, SMEM01);
    cudaFuncSetAttribute(gemm_mma<1>, cudaFuncAttributeMaxDynamicSharedMemorySize, SMEM01);
    cudaFuncSetAttribute(gemm_mma<2>, cudaFuncAttributeMaxDynamicSharedMemorySize, SMEM23);
    cudaFuncSetAttribute(gemm_mma<3>, cudaFuncAttributeMaxDynamicSharedMemorySize, SMEM23);

    dim3 blk(256);

    // converts
    conv_feat_k<<<(rows3 * 64 + 255) / 256, blk>>>(f_swin, f_maxvit, f_focal, rows3);
    conv_w_k<<<(768 * 64 + 255) / 256, blk>>>(in_proj_w, 768, WOFF_QKV);
    conv_w_k<<<(256 * 64 + 255) / 256, blk>>>(out_w, 256, WOFF_OUT);
    conv_w_k<<<(256 * 64 + 255) / 256, blk>>>(w1, 256, WOFF_W1);
    conv_w_k<<<(128 * 64 + 255) / 256, blk>>>(w2, 128, WOFF_W2);

    // qkv GEMM [3B, 768] (A bf16 single x W split)
    gemm_mma<0><<<dim3(6, rows3 / 128), blk, SMEM01>>>(in_proj_b, nullptr, nullptr, nullptr);
    // attention
    attn_k<<<(B + 7) / 8, blk>>>(B);
    // out-proj + residual [3B, 256] (A=ctx bf16 single x W split)
    gemm_mma<1><<<dim3(2, rows3 / 128), blk, SMEM01>>>(out_b, f_swin, f_maxvit, f_focal);
    // LN1 + gate + fused + LN2
    fuse_k<<<1024, blk>>>(f_swin, f_maxvit, f_focal,
                          ln1_g, ln1_b, gate_w, gate_b, ln2_g, ln2_b,
                          out_fused, B);
    // deep head (full split precision)
    gemm_mma<2><<<dim3(2, B / 128), blk, SMEM23>>>(b1, nullptr, nullptr, nullptr);
    gemm_mma<3><<<dim3(1, B / 128), blk, SMEM23>>>(b2, nullptr, nullptr, nullptr);
    logit_k<<<(B + 7) / 8, blk>>>(w3, b3, out_logits, B);
}